// round 14
// baseline (speedup 1.0000x reference)
#include <cuda_runtime.h>
#include <cuda_bf16.h>
#include <math.h>

#define NN   50000
#define EE   800000
#define IND  256
#define OUTD 128
#define DK   32
#define NEG  0.2f

// ---------------- scratch (device globals; no allocation allowed) ----------
__device__ float  d_Hproj[NN * OUTD];     // projected features [N,128]
__device__ float4 d_ssrc[NN];             // per-node <h, a_src> per head
__device__ float4 d_sdst[NN];             // per-node <h, a_dst> per head
__device__ float  d_M[NN * DK];           // per-node msg base  [N,32]
__device__ float4 d_rd[NN];               // per-node 1/(denom+eps) per head
__device__ float4 d_expe[EE];             // exp values, dst-bucket grouped
__device__ int    d_srcp[EE];             // src node, dst-bucket grouped
__device__ int    d_deg[NN];              // zero at entry (static init; k_out re-zeroes)
__device__ int    d_off[NN];
__device__ int    d_cur[NN];
__device__ int    d_total;                // reset in k_gemm prologue each call
// replay-idempotent accumulators (atomicMax with identical inputs)
__device__ unsigned d_gmax[4] = {0x007FFFFFu, 0x007FFFFFu, 0x007FFFFFu, 0x007FFFFFu};
__device__ int    d_idx64;                // 1 if edge_index is int64 (set by k_gemm blk0)

__device__ __forceinline__ unsigned f2okey(float f) {
    unsigned u = __float_as_uint(f);
    return (u & 0x80000000u) ? ~u : (u | 0x80000000u);
}
__device__ __forceinline__ float okey2f(unsigned k) {
    return __uint_as_float((k & 0x80000000u) ? (k ^ 0x80000000u) : ~k);
}

__device__ __forceinline__ void load_edge(const void* ei, int e, int& s, int& d) {
    if (d_idx64) {
        const long long* p = (const long long*)ei;
        s = (int)p[e]; d = (int)p[EE + e];
    } else {
        const int* p = (const int*)ei;
        s = p[e]; d = p[EE + e];
    }
}

// ---------------- K1: pipelined bf16-split HMMA GEMM + fused node pass ----
// Also: per-block dtype detect, d_total reset, and degree counting in the tail
// (d_deg is zero on entry: static init on call 1, k_out re-zeroes thereafter).
#define GBM 128
#define GBK 32
#define PADK 40
#define HPLD 132

__device__ __forceinline__ void mma16816(float* c, const unsigned* a,
                                         unsigned b0, unsigned b1) {
    asm volatile(
        "mma.sync.aligned.m16n8k16.row.col.f32.bf16.bf16.f32 "
        "{%0,%1,%2,%3}, {%4,%5,%6,%7}, {%8,%9}, {%0,%1,%2,%3};"
        : "+f"(c[0]), "+f"(c[1]), "+f"(c[2]), "+f"(c[3])
        : "r"(a[0]), "r"(a[1]), "r"(a[2]), "r"(a[3]), "r"(b0), "r"(b1));
}

__device__ __forceinline__ __nv_bfloat16* stg(char* base, int st, int which) {
    return (__nv_bfloat16*)base + ((size_t)(st * 4 + which)) * GBM * PADK;
}

__global__ void __launch_bounds__(256) k_gemm_mma(const float* __restrict__ H,
                                                  const float* __restrict__ W,
                                                  const float* __restrict__ asrc,
                                                  const float* __restrict__ adst,
                                                  const float* __restrict__ mw,
                                                  const unsigned* __restrict__ eiw) {
    extern __shared__ char dsm[];
    __shared__ float s_as[128], s_ad[128];
    __shared__ float s_mwT[DK * DK];       // transposed: [l][o]
    __shared__ float s_hm[8][32];
    __shared__ int   s_i64;

    int tid  = threadIdx.x;
    int lane = tid & 31;
    int warp = tid >> 5;
    int wm   = warp >> 1;
    int wn   = warp & 1;
    int m0   = blockIdx.x * GBM;
    int gid  = blockIdx.x * 256 + tid;

    // per-block dtype detect (int32 => odd words are uniform indices in
    // [0,50000); 64 consecutive zeros impossible. int64 => high halves zero).
    if (tid == 0) {
        unsigned v = 0;
#pragma unroll
        for (int i = 0; i < 64; i++) v |= eiw[2 * i + 1];
        s_i64 = (v == 0u) ? 1 : 0;
        if (blockIdx.x == 0) { d_idx64 = s_i64; d_total = 0; }
    }
    if (tid < 128) { s_as[tid] = asrc[tid]; s_ad[tid] = adst[tid]; }
    for (int idx = tid; idx < DK * DK; idx += 256) {
        int o = idx >> 5, l = idx & 31;
        s_mwT[l * 32 + o] = mw[idx];
    }

    float acc[2][8][4];
#pragma unroll
    for (int mi = 0; mi < 2; mi++)
#pragma unroll
        for (int ni = 0; ni < 8; ni++)
#pragma unroll
            for (int q = 0; q < 4; q++) acc[mi][ni][q] = 0.f;

    int lr = tid >> 3;          // 0..31
    int kc = (tid & 7) * 4;     // float4 col within 32-chunk

    float4 ra[4], rb[4];

    // ---- prologue: load + convert chunk 0 into stage 0
#pragma unroll
    for (int j = 0; j < 4; j++) {
        int gr = m0 + j * 32 + lr;
        ra[j] = make_float4(0.f, 0.f, 0.f, 0.f);
        if (gr < NN) ra[j] = *(const float4*)&H[(size_t)gr * IND + kc];
        rb[j] = *(const float4*)&W[(size_t)(j * 32 + lr) * IND + kc];
    }
    {
        __nv_bfloat16 *pAh = stg(dsm, 0, 0), *pAl = stg(dsm, 0, 1);
        __nv_bfloat16 *pBh = stg(dsm, 0, 2), *pBl = stg(dsm, 0, 3);
#pragma unroll
        for (int j = 0; j < 4; j++) {
            int r = j * 32 + lr;
            float4 v = ra[j];
            __nv_bfloat16 hx = __float2bfloat16_rn(v.x), hy = __float2bfloat16_rn(v.y);
            __nv_bfloat16 hz = __float2bfloat16_rn(v.z), hw = __float2bfloat16_rn(v.w);
            *(__nv_bfloat162*)&pAh[r * PADK + kc]     = __nv_bfloat162(hx, hy);
            *(__nv_bfloat162*)&pAh[r * PADK + kc + 2] = __nv_bfloat162(hz, hw);
            *(__nv_bfloat162*)&pAl[r * PADK + kc] = __nv_bfloat162(
                __float2bfloat16_rn(v.x - __bfloat162float(hx)),
                __float2bfloat16_rn(v.y - __bfloat162float(hy)));
            *(__nv_bfloat162*)&pAl[r * PADK + kc + 2] = __nv_bfloat162(
                __float2bfloat16_rn(v.z - __bfloat162float(hz)),
                __float2bfloat16_rn(v.w - __bfloat162float(hw)));
            v = rb[j];
            hx = __float2bfloat16_rn(v.x); hy = __float2bfloat16_rn(v.y);
            hz = __float2bfloat16_rn(v.z); hw = __float2bfloat16_rn(v.w);
            *(__nv_bfloat162*)&pBh[r * PADK + kc]     = __nv_bfloat162(hx, hy);
            *(__nv_bfloat162*)&pBh[r * PADK + kc + 2] = __nv_bfloat162(hz, hw);
            *(__nv_bfloat162*)&pBl[r * PADK + kc] = __nv_bfloat162(
                __float2bfloat16_rn(v.x - __bfloat162float(hx)),
                __float2bfloat16_rn(v.y - __bfloat162float(hy)));
            *(__nv_bfloat162*)&pBl[r * PADK + kc + 2] = __nv_bfloat162(
                __float2bfloat16_rn(v.z - __bfloat162float(hz)),
                __float2bfloat16_rn(v.w - __bfloat162float(hw)));
        }
    }
    __syncthreads();

    // ---- main loop over 8 k-chunks, 2-stage pipeline
#pragma unroll 1
    for (int c = 0; c < 8; c++) {
        int st = c & 1;
        if (c < 7) {
            int k0 = (c + 1) * GBK;
#pragma unroll
            for (int j = 0; j < 4; j++) {
                int gr = m0 + j * 32 + lr;
                ra[j] = make_float4(0.f, 0.f, 0.f, 0.f);
                if (gr < NN) ra[j] = *(const float4*)&H[(size_t)gr * IND + k0 + kc];
                rb[j] = *(const float4*)&W[(size_t)(j * 32 + lr) * IND + k0 + kc];
            }
        }
        {
            __nv_bfloat16 *pAh = stg(dsm, st, 0), *pAl = stg(dsm, st, 1);
            __nv_bfloat16 *pBh = stg(dsm, st, 2), *pBl = stg(dsm, st, 3);
#pragma unroll
            for (int p = 0; p < 3; p++) {
                const __nv_bfloat16* At = (p == 2) ? pAl : pAh;
                const __nv_bfloat16* Bt = (p == 1) ? pBl : pBh;
#pragma unroll
                for (int ks = 0; ks < 2; ks++) {
                    int cc = ks * 16 + (lane & 3) * 2;
                    unsigned a[2][4];
#pragma unroll
                    for (int mi = 0; mi < 2; mi++) {
                        int r = wm * 32 + mi * 16 + (lane >> 2);
                        a[mi][0] = *(const unsigned*)&At[r * PADK + cc];
                        a[mi][1] = *(const unsigned*)&At[(r + 8) * PADK + cc];
                        a[mi][2] = *(const unsigned*)&At[r * PADK + cc + 8];
                        a[mi][3] = *(const unsigned*)&At[(r + 8) * PADK + cc + 8];
                    }
#pragma unroll
                    for (int ni = 0; ni < 8; ni++) {
                        int n = wn * 64 + ni * 8 + (lane >> 2);
                        unsigned b0 = *(const unsigned*)&Bt[n * PADK + cc];
                        unsigned b1 = *(const unsigned*)&Bt[n * PADK + cc + 8];
                        mma16816(acc[0][ni], a[0], b0, b1);
                        mma16816(acc[1][ni], a[1], b0, b1);
                    }
                }
            }
        }
        if (c < 7) {
            int ns = st ^ 1;
            __nv_bfloat16 *pAh = stg(dsm, ns, 0), *pAl = stg(dsm, ns, 1);
            __nv_bfloat16 *pBh = stg(dsm, ns, 2), *pBl = stg(dsm, ns, 3);
#pragma unroll
            for (int j = 0; j < 4; j++) {
                int r = j * 32 + lr;
                float4 v = ra[j];
                __nv_bfloat16 hx = __float2bfloat16_rn(v.x), hy = __float2bfloat16_rn(v.y);
                __nv_bfloat16 hz = __float2bfloat16_rn(v.z), hw = __float2bfloat16_rn(v.w);
                *(__nv_bfloat162*)&pAh[r * PADK + kc]     = __nv_bfloat162(hx, hy);
                *(__nv_bfloat162*)&pAh[r * PADK + kc + 2] = __nv_bfloat162(hz, hw);
                *(__nv_bfloat162*)&pAl[r * PADK + kc] = __nv_bfloat162(
                    __float2bfloat16_rn(v.x - __bfloat162float(hx)),
                    __float2bfloat16_rn(v.y - __bfloat162float(hy)));
                *(__nv_bfloat162*)&pAl[r * PADK + kc + 2] = __nv_bfloat162(
                    __float2bfloat16_rn(v.z - __bfloat162float(hz)),
                    __float2bfloat16_rn(v.w - __bfloat162float(hw)));
                v = rb[j];
                hx = __float2bfloat16_rn(v.x); hy = __float2bfloat16_rn(v.y);
                hz = __float2bfloat16_rn(v.z); hw = __float2bfloat16_rn(v.w);
                *(__nv_bfloat162*)&pBh[r * PADK + kc]     = __nv_bfloat162(hx, hy);
                *(__nv_bfloat162*)&pBh[r * PADK + kc + 2] = __nv_bfloat162(hz, hw);
                *(__nv_bfloat162*)&pBl[r * PADK + kc] = __nv_bfloat162(
                    __float2bfloat16_rn(v.x - __bfloat162float(hx)),
                    __float2bfloat16_rn(v.y - __bfloat162float(hy)));
                *(__nv_bfloat162*)&pBl[r * PADK + kc + 2] = __nv_bfloat162(
                    __float2bfloat16_rn(v.z - __bfloat162float(hz)),
                    __float2bfloat16_rn(v.w - __bfloat162float(hw)));
            }
        }
        __syncthreads();
    }

    // ---- epilogue 1: store tile to smem (aliased) + global
    float* Hp = (float*)dsm;
#pragma unroll
    for (int mi = 0; mi < 2; mi++) {
        int r0 = wm * 32 + mi * 16 + (lane >> 2);
#pragma unroll
        for (int ni = 0; ni < 8; ni++) {
            int cg = wn * 64 + ni * 8 + (lane & 3) * 2;
            Hp[r0 * HPLD + cg]           = acc[mi][ni][0];
            Hp[r0 * HPLD + cg + 1]       = acc[mi][ni][1];
            Hp[(r0 + 8) * HPLD + cg]     = acc[mi][ni][2];
            Hp[(r0 + 8) * HPLD + cg + 1] = acc[mi][ni][3];
            if (m0 + r0 < NN)
                *(float2*)&d_Hproj[(size_t)(m0 + r0) * OUTD + cg] =
                    make_float2(acc[mi][ni][0], acc[mi][ni][1]);
            if (m0 + r0 + 8 < NN)
                *(float2*)&d_Hproj[(size_t)(m0 + r0 + 8) * OUTD + cg] =
                    make_float2(acc[mi][ni][2], acc[mi][ni][3]);
        }
    }
    __syncthreads();

    // ---- epilogue 2: fused node pass (s_src, s_dst, M) — 16 rows per warp
    for (int rr = 0; rr < 16; rr++) {
        int r = warp * 16 + rr;
        int node = m0 + r;
        float v0 = Hp[r * HPLD + 0 * 32 + lane];
        float v1 = Hp[r * HPLD + 1 * 32 + lane];
        float v2 = Hp[r * HPLD + 2 * 32 + lane];
        float v3 = Hp[r * HPLD + 3 * 32 + lane];
        float p0 = v0 * s_as[lane],       q0 = v0 * s_ad[lane];
        float p1 = v1 * s_as[32 + lane],  q1 = v1 * s_ad[32 + lane];
        float p2 = v2 * s_as[64 + lane],  q2 = v2 * s_ad[64 + lane];
        float p3 = v3 * s_as[96 + lane],  q3 = v3 * s_ad[96 + lane];
#pragma unroll
        for (int o = 16; o; o >>= 1) {
            p0 += __shfl_xor_sync(0xffffffffu, p0, o);
            p1 += __shfl_xor_sync(0xffffffffu, p1, o);
            p2 += __shfl_xor_sync(0xffffffffu, p2, o);
            p3 += __shfl_xor_sync(0xffffffffu, p3, o);
            q0 += __shfl_xor_sync(0xffffffffu, q0, o);
            q1 += __shfl_xor_sync(0xffffffffu, q1, o);
            q2 += __shfl_xor_sync(0xffffffffu, q2, o);
            q3 += __shfl_xor_sync(0xffffffffu, q3, o);
        }
        if (node < NN && lane == 0) {
            d_ssrc[node] = make_float4(p0, p1, p2, p3);
            d_sdst[node] = make_float4(q0, q1, q2, q3);
        }
        float hm = 0.25f * (v0 + v1 + v2 + v3);
        s_hm[warp][lane] = hm;
        __syncwarp();
        float m = 0.f;
#pragma unroll
        for (int l = 0; l < 32; l++) m += s_hm[warp][l] * s_mwT[l * 32 + lane];
        if (node < NN) d_M[(size_t)node * DK + lane] = m;
        __syncwarp();
    }

    // ---- tail: degree counting (overlaps with other blocks' MMA work)
    {
        int gstep = gridDim.x * 256;
        if (s_i64) {
            const long long* p = (const long long*)eiw;
            for (int e = gid; e < EE; e += gstep)
                atomicAdd(&d_deg[(int)p[EE + e]], 1);
        } else {
            const int* p = (const int*)eiw;
            for (int e = gid; e < EE; e += gstep)
                atomicAdd(&d_deg[p[EE + e]], 1);
        }
    }
}

// ---------------- K2: edge pass 1 (global per-head max only) --------------
__global__ void __launch_bounds__(256) k_edge1(const void* __restrict__ ei,
                                               const float* __restrict__ sim) {
    int e = blockIdx.x * 256 + threadIdx.x;
    int lane = threadIdx.x & 31, warp = threadIdx.x >> 5;
    float4 l = make_float4(-INFINITY, -INFINITY, -INFINITY, -INFINITY);
    if (e < EE) {
        int s, d;
        load_edge(ei, e, s, d);
        float4 a = d_ssrc[s];
        float4 b = d_sdst[d];
        float si = sim[e];
        l.x = a.x + b.x + si; l.y = a.y + b.y + si;
        l.z = a.z + b.z + si; l.w = a.w + b.w + si;
        // LeakyReLU deferred to after max (monotone => commutes with max)
    }
    float4 m = l;
#pragma unroll
    for (int o = 16; o; o >>= 1) {
        m.x = fmaxf(m.x, __shfl_xor_sync(0xffffffffu, m.x, o));
        m.y = fmaxf(m.y, __shfl_xor_sync(0xffffffffu, m.y, o));
        m.z = fmaxf(m.z, __shfl_xor_sync(0xffffffffu, m.z, o));
        m.w = fmaxf(m.w, __shfl_xor_sync(0xffffffffu, m.w, o));
    }
    __shared__ float4 swm[8];
    if (lane == 0) swm[warp] = m;
    __syncthreads();
    if (warp == 0) {
        float4 mm = (lane < 8) ? swm[lane]
                               : make_float4(-INFINITY, -INFINITY, -INFINITY, -INFINITY);
#pragma unroll
        for (int o = 4; o; o >>= 1) {
            mm.x = fmaxf(mm.x, __shfl_xor_sync(0xffffffffu, mm.x, o));
            mm.y = fmaxf(mm.y, __shfl_xor_sync(0xffffffffu, mm.y, o));
            mm.z = fmaxf(mm.z, __shfl_xor_sync(0xffffffffu, mm.z, o));
            mm.w = fmaxf(mm.w, __shfl_xor_sync(0xffffffffu, mm.w, o));
        }
        if (lane == 0) {
            mm.x = mm.x >= 0.f ? mm.x : NEG * mm.x;
            mm.y = mm.y >= 0.f ? mm.y : NEG * mm.y;
            mm.z = mm.z >= 0.f ? mm.z : NEG * mm.z;
            mm.w = mm.w >= 0.f ? mm.w : NEG * mm.w;
            atomicMax(&d_gmax[0], f2okey(mm.x));
            atomicMax(&d_gmax[1], f2okey(mm.y));
            atomicMax(&d_gmax[2], f2okey(mm.z));
            atomicMax(&d_gmax[3], f2okey(mm.w));
        }
    }
}

// ---------------- K3: bucket offsets via warp-batched atomic --------------
__global__ void k_off() {
    int i = blockIdx.x * 256 + threadIdx.x;
    int lane = threadIdx.x & 31;
    int v = (i < NN) ? d_deg[i] : 0;
    int x = v;
#pragma unroll
    for (int o = 1; o < 32; o <<= 1) {
        int y = __shfl_up_sync(0xffffffffu, x, o);
        if (lane >= o) x += y;
    }
    int excl = x - v;
    int tot = __shfl_sync(0xffffffffu, x, 31);
    int base = 0;
    if (lane == 31) base = atomicAdd(&d_total, tot);
    base = __shfl_sync(0xffffffffu, base, 31);
    if (i < NN) { d_off[i] = base + excl; d_cur[i] = base + excl; }
}

// ---------------- K4: edge pass 2 (recompute logits, exp, scatter) --------
__global__ void __launch_bounds__(256) k_edge2(const void* __restrict__ ei,
                                               const float* __restrict__ sim) {
    int e = blockIdx.x * 256 + threadIdx.x;
    if (e >= EE) return;
    int s, d;
    load_edge(ei, e, s, d);
    float4 a = d_ssrc[s];
    float4 b = d_sdst[d];
    float si = sim[e];
    float4 l;
    l.x = a.x + b.x + si; l.y = a.y + b.y + si;
    l.z = a.z + b.z + si; l.w = a.w + b.w + si;
    l.x = l.x >= 0.f ? l.x : NEG * l.x;
    l.y = l.y >= 0.f ? l.y : NEG * l.y;
    l.z = l.z >= 0.f ? l.z : NEG * l.z;
    l.w = l.w >= 0.f ? l.w : NEG * l.w;
    float g0 = okey2f(d_gmax[0]), g1 = okey2f(d_gmax[1]);
    float g2 = okey2f(d_gmax[2]), g3 = okey2f(d_gmax[3]);
    float4 ex = make_float4(expf(l.x - g0), expf(l.y - g1),
                            expf(l.z - g2), expf(l.w - g3));
    int pos = atomicAdd(&d_cur[d], 1);
    d_expe[pos] = ex;
    d_srcp[pos] = s;
}

// ---------------- K5: per-dst softmax + aggregation, shuffle-batched ------
__global__ void __launch_bounds__(256) k_out(float* __restrict__ out_h) {
    int tid = threadIdx.x, lane = tid & 31, warp = tid >> 5;
    int node = blockIdx.x * 8 + warp;
    if (node >= NN) return;
    int start = d_off[node];
    int deg   = d_deg[node];
    if (lane == 0) d_deg[node] = 0;      // restore zero for next call's gemm count

    int myh = lane >> 3;
    float4 den = make_float4(0.f, 0.f, 0.f, 0.f);
    float4 acc = make_float4(0.f, 0.f, 0.f, 0.f);
    for (int base = 0; base < deg; base += 32) {
        int n = deg - base; if (n > 32) n = 32;
        float4 exv = make_float4(0.f, 0.f, 0.f, 0.f);
        int sv = 0;
        if (lane < n) {                   // coalesced chunk load
            exv = d_expe[start + base + lane];
            sv  = d_srcp[start + base + lane];
        }
        den.x += exv.x; den.y += exv.y; den.z += exv.z; den.w += exv.w;
#pragma unroll 4
        for (int j = 0; j < n; j++) {
            float ax = __shfl_sync(0xffffffffu, exv.x, j);
            float ay = __shfl_sync(0xffffffffu, exv.y, j);
            float az = __shfl_sync(0xffffffffu, exv.z, j);
            float aw = __shfl_sync(0xffffffffu, exv.w, j);
            int   s  = __shfl_sync(0xffffffffu, sv, j);
            float a = (myh == 0) ? ax : (myh == 1) ? ay : (myh == 2) ? az : aw;
            float4 hv = *(const float4*)&d_Hproj[(size_t)s * OUTD + (lane << 2)];
            acc.x += a * hv.x; acc.y += a * hv.y;
            acc.z += a * hv.z; acc.w += a * hv.w;
        }
    }
#pragma unroll
    for (int o = 16; o; o >>= 1) {
        den.x += __shfl_xor_sync(0xffffffffu, den.x, o);
        den.y += __shfl_xor_sync(0xffffffffu, den.y, o);
        den.z += __shfl_xor_sync(0xffffffffu, den.z, o);
        den.w += __shfl_xor_sync(0xffffffffu, den.w, o);
    }
    float4 rd = make_float4(1.f / (den.x + 1e-12f), 1.f / (den.y + 1e-12f),
                            1.f / (den.z + 1e-12f), 1.f / (den.w + 1e-12f));
    if (lane == 0) d_rd[node] = rd;
    float r = (myh == 0) ? rd.x : (myh == 1) ? rd.y : (myh == 2) ? rd.z : rd.w;
    *(float4*)&out_h[(size_t)node * OUTD + (lane << 2)] =
        make_float4(acc.x * r, acc.y * r, acc.z * r, acc.w * r);
}

// ---------------- K6: fused msg copy + coalesced alpha ---------------------
#define MSGB (EE * 8 / 256)   // 25000 blocks for msg copy
#define ALPB (EE / 256)       // 3125 blocks for alpha
__global__ void __launch_bounds__(256) k_post(const void* __restrict__ ei,
                                              const float* __restrict__ sim,
                                              float* __restrict__ out_msg,
                                              float* __restrict__ out_alpha) {
    if (blockIdx.x < MSGB) {
        int idx = blockIdx.x * 256 + threadIdx.x;
        int e = idx >> 3;
        int q = (idx & 7) << 2;
        int s, d;
        load_edge(ei, e, s, d);
        float4 v = *(const float4*)&d_M[(size_t)s * DK + q];
        *(float4*)&out_msg[(size_t)e * DK + q] = v;
    } else {
        int e = (blockIdx.x - MSGB) * 256 + threadIdx.x;
        if (e >= EE) return;
        int s, d;
        load_edge(ei, e, s, d);
        float4 a = d_ssrc[s];
        float4 b = d_sdst[d];
        float si = sim[e];
        float4 l;
        l.x = a.x + b.x + si; l.y = a.y + b.y + si;
        l.z = a.z + b.z + si; l.w = a.w + b.w + si;
        l.x = l.x >= 0.f ? l.x : NEG * l.x;
        l.y = l.y >= 0.f ? l.y : NEG * l.y;
        l.z = l.z >= 0.f ? l.z : NEG * l.z;
        l.w = l.w >= 0.f ? l.w : NEG * l.w;
        float g0 = okey2f(d_gmax[0]), g1 = okey2f(d_gmax[1]);
        float g2 = okey2f(d_gmax[2]), g3 = okey2f(d_gmax[3]);
        float4 rd = d_rd[d];
        out_alpha[e] = 0.25f * (expf(l.x - g0) * rd.x + expf(l.y - g1) * rd.y +
                                expf(l.z - g2) * rd.z + expf(l.w - g3) * rd.w);
    }
}

// ---------------- launcher ------------------------------------------------
#define GEMM_SMEM 81920   // 2 stages x 4 arrays x 128x40 bf16; epilogue 128x132 f32 fits

extern "C" void kernel_launch(void* const* d_in, const int* in_sizes, int n_in,
                              void* d_out, int out_size) {
    const float* H    = (const float*)d_in[0];
    const void*  ei   = d_in[1];
    const float* sim  = (const float*)d_in[2];
    const float* W    = (const float*)d_in[3];
    const float* asrc = (const float*)d_in[4];
    const float* adst = (const float*)d_in[5];
    const float* mw   = (const float*)d_in[6];

    float* out       = (float*)d_out;
    float* out_h     = out;                       // [N,128]
    float* out_alpha = out + (size_t)NN * OUTD;   // [E]
    float* out_msg   = out_alpha + EE;            // [E,32]

    cudaFuncSetAttribute(k_gemm_mma,
                         cudaFuncAttributeMaxDynamicSharedMemorySize, GEMM_SMEM);

    k_gemm_mma<<<(NN + GBM - 1) / GBM, 256, GEMM_SMEM>>>(H, W, asrc, adst, mw,
                                                         (const unsigned*)ei);
    k_edge1   <<<EE / 256, 256>>>(ei, sim);
    k_off     <<<(NN + 255) / 256, 256>>>();
    k_edge2   <<<EE / 256, 256>>>(ei, sim);
    k_out     <<<(NN + 7) / 8, 256>>>(out_h);
    k_post    <<<MSGB + ALPB, 256>>>(ei, sim, out_msg, out_alpha);
}

// round 16
// speedup vs baseline: 1.2380x; 1.2380x over previous
#include <cuda_runtime.h>
#include <cuda_bf16.h>
#include <cuda_fp16.h>
#include <math.h>

#define NN   50000
#define EE   800000
#define IND  256
#define OUTD 128
#define DK   32
#define NEG  0.2f

// ---------------- scratch (device globals; no allocation allowed) ----------
__device__ __half d_Hp16[NN * OUTD];      // projected features, fp16 (k_out only)
__device__ float4 d_ssrc[NN];             // per-node <h, a_src> per head
__device__ float4 d_sdst[NN];             // per-node <h, a_dst> per head
__device__ float  d_M[NN * DK];           // per-node msg base  [N,32]
__device__ float4 d_rd[NN];               // per-node 1/(denom+eps) per head
__device__ float4 d_expe[EE];             // exp values, dst-bucket grouped
__device__ int    d_srcp[EE];             // src node, dst-bucket grouped
__device__ int    d_deg[NN];              // zeroed in k_gemm prologue each call
__device__ int    d_off[NN];
__device__ int    d_cur[NN];
__device__ int    d_total;                // reset in k_gemm prologue each call
// replay-idempotent accumulators (atomicMax with identical inputs)
__device__ unsigned d_gmax[4] = {0x007FFFFFu, 0x007FFFFFu, 0x007FFFFFu, 0x007FFFFFu};
__device__ int    d_idx64;                // 1 if edge_index is int64 (set by k_gemm blk0)

__device__ __forceinline__ unsigned f2okey(float f) {
    unsigned u = __float_as_uint(f);
    return (u & 0x80000000u) ? ~u : (u | 0x80000000u);
}
__device__ __forceinline__ float okey2f(unsigned k) {
    return __uint_as_float((k & 0x80000000u) ? (k ^ 0x80000000u) : ~k);
}

__device__ __forceinline__ void load_edge(const void* ei, int e, int& s, int& d) {
    if (d_idx64) {
        const long long* p = (const long long*)ei;
        s = (int)p[e]; d = (int)p[EE + e];
    } else {
        const int* p = (const int*)ei;
        s = p[e]; d = p[EE + e];
    }
}

// ---------------- K1: pipelined bf16-split HMMA GEMM + fused node pass ----
#define GBM 128
#define GBK 32
#define PADK 40
#define HPLD 132

__device__ __forceinline__ void mma16816(float* c, const unsigned* a,
                                         unsigned b0, unsigned b1) {
    asm volatile(
        "mma.sync.aligned.m16n8k16.row.col.f32.bf16.bf16.f32 "
        "{%0,%1,%2,%3}, {%4,%5,%6,%7}, {%8,%9}, {%0,%1,%2,%3};"
        : "+f"(c[0]), "+f"(c[1]), "+f"(c[2]), "+f"(c[3])
        : "r"(a[0]), "r"(a[1]), "r"(a[2]), "r"(a[3]), "r"(b0), "r"(b1));
}

__device__ __forceinline__ __nv_bfloat16* stg(char* base, int st, int which) {
    return (__nv_bfloat16*)base + ((size_t)(st * 4 + which)) * GBM * PADK;
}

__global__ void __launch_bounds__(256) k_gemm_mma(const float* __restrict__ H,
                                                  const float* __restrict__ W,
                                                  const float* __restrict__ asrc,
                                                  const float* __restrict__ adst,
                                                  const float* __restrict__ mw,
                                                  const unsigned* __restrict__ eiw) {
    extern __shared__ char dsm[];
    __shared__ float s_as[128], s_ad[128];
    __shared__ float s_mwT[DK * DK];       // transposed: [l][o]
    __shared__ float s_hm[8][32];

    int tid  = threadIdx.x;
    int lane = tid & 31;
    int warp = tid >> 5;
    int wm   = warp >> 1;
    int wn   = warp & 1;
    int m0   = blockIdx.x * GBM;

    // prologue housekeeping: zero d_deg, reset d_total, detect index dtype.
    int gid = blockIdx.x * 256 + tid;
    if (gid < NN) d_deg[gid] = 0;
    if (gid == 0) {
        d_total = 0;
        unsigned v = 0;
#pragma unroll
        for (int i = 0; i < 64; i++) v |= eiw[2 * i + 1];
        d_idx64 = (v == 0u) ? 1 : 0;
    }
    if (tid < 128) { s_as[tid] = asrc[tid]; s_ad[tid] = adst[tid]; }
    for (int idx = tid; idx < DK * DK; idx += 256) {
        int o = idx >> 5, l = idx & 31;
        s_mwT[l * 32 + o] = mw[idx];
    }

    float acc[2][8][4];
#pragma unroll
    for (int mi = 0; mi < 2; mi++)
#pragma unroll
        for (int ni = 0; ni < 8; ni++)
#pragma unroll
            for (int q = 0; q < 4; q++) acc[mi][ni][q] = 0.f;

    int lr = tid >> 3;          // 0..31
    int kc = (tid & 7) * 4;     // float4 col within 32-chunk

    float4 ra[4], rb[4];

    // ---- prologue: load + convert chunk 0 into stage 0
#pragma unroll
    for (int j = 0; j < 4; j++) {
        int gr = m0 + j * 32 + lr;
        ra[j] = make_float4(0.f, 0.f, 0.f, 0.f);
        if (gr < NN) ra[j] = *(const float4*)&H[(size_t)gr * IND + kc];
        rb[j] = *(const float4*)&W[(size_t)(j * 32 + lr) * IND + kc];
    }
    {
        __nv_bfloat16 *pAh = stg(dsm, 0, 0), *pAl = stg(dsm, 0, 1);
        __nv_bfloat16 *pBh = stg(dsm, 0, 2), *pBl = stg(dsm, 0, 3);
#pragma unroll
        for (int j = 0; j < 4; j++) {
            int r = j * 32 + lr;
            float4 v = ra[j];
            __nv_bfloat16 hx = __float2bfloat16_rn(v.x), hy = __float2bfloat16_rn(v.y);
            __nv_bfloat16 hz = __float2bfloat16_rn(v.z), hw = __float2bfloat16_rn(v.w);
            *(__nv_bfloat162*)&pAh[r * PADK + kc]     = __nv_bfloat162(hx, hy);
            *(__nv_bfloat162*)&pAh[r * PADK + kc + 2] = __nv_bfloat162(hz, hw);
            *(__nv_bfloat162*)&pAl[r * PADK + kc] = __nv_bfloat162(
                __float2bfloat16_rn(v.x - __bfloat162float(hx)),
                __float2bfloat16_rn(v.y - __bfloat162float(hy)));
            *(__nv_bfloat162*)&pAl[r * PADK + kc + 2] = __nv_bfloat162(
                __float2bfloat16_rn(v.z - __bfloat162float(hz)),
                __float2bfloat16_rn(v.w - __bfloat162float(hw)));
            v = rb[j];
            hx = __float2bfloat16_rn(v.x); hy = __float2bfloat16_rn(v.y);
            hz = __float2bfloat16_rn(v.z); hw = __float2bfloat16_rn(v.w);
            *(__nv_bfloat162*)&pBh[r * PADK + kc]     = __nv_bfloat162(hx, hy);
            *(__nv_bfloat162*)&pBh[r * PADK + kc + 2] = __nv_bfloat162(hz, hw);
            *(__nv_bfloat162*)&pBl[r * PADK + kc] = __nv_bfloat162(
                __float2bfloat16_rn(v.x - __bfloat162float(hx)),
                __float2bfloat16_rn(v.y - __bfloat162float(hy)));
            *(__nv_bfloat162*)&pBl[r * PADK + kc + 2] = __nv_bfloat162(
                __float2bfloat16_rn(v.z - __bfloat162float(hz)),
                __float2bfloat16_rn(v.w - __bfloat162float(hw)));
        }
    }
    __syncthreads();

    // ---- main loop over 8 k-chunks, 2-stage pipeline
#pragma unroll 1
    for (int c = 0; c < 8; c++) {
        int st = c & 1;
        if (c < 7) {
            int k0 = (c + 1) * GBK;
#pragma unroll
            for (int j = 0; j < 4; j++) {
                int gr = m0 + j * 32 + lr;
                ra[j] = make_float4(0.f, 0.f, 0.f, 0.f);
                if (gr < NN) ra[j] = *(const float4*)&H[(size_t)gr * IND + k0 + kc];
                rb[j] = *(const float4*)&W[(size_t)(j * 32 + lr) * IND + k0 + kc];
            }
        }
        {
            __nv_bfloat16 *pAh = stg(dsm, st, 0), *pAl = stg(dsm, st, 1);
            __nv_bfloat16 *pBh = stg(dsm, st, 2), *pBl = stg(dsm, st, 3);
#pragma unroll
            for (int p = 0; p < 3; p++) {
                const __nv_bfloat16* At = (p == 2) ? pAl : pAh;
                const __nv_bfloat16* Bt = (p == 1) ? pBl : pBh;
#pragma unroll
                for (int ks = 0; ks < 2; ks++) {
                    int cc = ks * 16 + (lane & 3) * 2;
                    unsigned a[2][4];
#pragma unroll
                    for (int mi = 0; mi < 2; mi++) {
                        int r = wm * 32 + mi * 16 + (lane >> 2);
                        a[mi][0] = *(const unsigned*)&At[r * PADK + cc];
                        a[mi][1] = *(const unsigned*)&At[(r + 8) * PADK + cc];
                        a[mi][2] = *(const unsigned*)&At[r * PADK + cc + 8];
                        a[mi][3] = *(const unsigned*)&At[(r + 8) * PADK + cc + 8];
                    }
#pragma unroll
                    for (int ni = 0; ni < 8; ni++) {
                        int n = wn * 64 + ni * 8 + (lane >> 2);
                        unsigned b0 = *(const unsigned*)&Bt[n * PADK + cc];
                        unsigned b1 = *(const unsigned*)&Bt[n * PADK + cc + 8];
                        mma16816(acc[0][ni], a[0], b0, b1);
                        mma16816(acc[1][ni], a[1], b0, b1);
                    }
                }
            }
        }
        if (c < 7) {
            int ns = st ^ 1;
            __nv_bfloat16 *pAh = stg(dsm, ns, 0), *pAl = stg(dsm, ns, 1);
            __nv_bfloat16 *pBh = stg(dsm, ns, 2), *pBl = stg(dsm, ns, 3);
#pragma unroll
            for (int j = 0; j < 4; j++) {
                int r = j * 32 + lr;
                float4 v = ra[j];
                __nv_bfloat16 hx = __float2bfloat16_rn(v.x), hy = __float2bfloat16_rn(v.y);
                __nv_bfloat16 hz = __float2bfloat16_rn(v.z), hw = __float2bfloat16_rn(v.w);
                *(__nv_bfloat162*)&pAh[r * PADK + kc]     = __nv_bfloat162(hx, hy);
                *(__nv_bfloat162*)&pAh[r * PADK + kc + 2] = __nv_bfloat162(hz, hw);
                *(__nv_bfloat162*)&pAl[r * PADK + kc] = __nv_bfloat162(
                    __float2bfloat16_rn(v.x - __bfloat162float(hx)),
                    __float2bfloat16_rn(v.y - __bfloat162float(hy)));
                *(__nv_bfloat162*)&pAl[r * PADK + kc + 2] = __nv_bfloat162(
                    __float2bfloat16_rn(v.z - __bfloat162float(hz)),
                    __float2bfloat16_rn(v.w - __bfloat162float(hw)));
                v = rb[j];
                hx = __float2bfloat16_rn(v.x); hy = __float2bfloat16_rn(v.y);
                hz = __float2bfloat16_rn(v.z); hw = __float2bfloat16_rn(v.w);
                *(__nv_bfloat162*)&pBh[r * PADK + kc]     = __nv_bfloat162(hx, hy);
                *(__nv_bfloat162*)&pBh[r * PADK + kc + 2] = __nv_bfloat162(hz, hw);
                *(__nv_bfloat162*)&pBl[r * PADK + kc] = __nv_bfloat162(
                    __float2bfloat16_rn(v.x - __bfloat162float(hx)),
                    __float2bfloat16_rn(v.y - __bfloat162float(hy)));
                *(__nv_bfloat162*)&pBl[r * PADK + kc + 2] = __nv_bfloat162(
                    __float2bfloat16_rn(v.z - __bfloat162float(hz)),
                    __float2bfloat16_rn(v.w - __bfloat162float(hw)));
            }
        }
        __syncthreads();
    }

    // ---- epilogue 1: store tile to smem (aliased) + fp16 global copy
    float* Hp = (float*)dsm;
#pragma unroll
    for (int mi = 0; mi < 2; mi++) {
        int r0 = wm * 32 + mi * 16 + (lane >> 2);
#pragma unroll
        for (int ni = 0; ni < 8; ni++) {
            int cg = wn * 64 + ni * 8 + (lane & 3) * 2;
            Hp[r0 * HPLD + cg]           = acc[mi][ni][0];
            Hp[r0 * HPLD + cg + 1]       = acc[mi][ni][1];
            Hp[(r0 + 8) * HPLD + cg]     = acc[mi][ni][2];
            Hp[(r0 + 8) * HPLD + cg + 1] = acc[mi][ni][3];
            if (m0 + r0 < NN)
                *(__half2*)&d_Hp16[(size_t)(m0 + r0) * OUTD + cg] =
                    __floats2half2_rn(acc[mi][ni][0], acc[mi][ni][1]);
            if (m0 + r0 + 8 < NN)
                *(__half2*)&d_Hp16[(size_t)(m0 + r0 + 8) * OUTD + cg] =
                    __floats2half2_rn(acc[mi][ni][2], acc[mi][ni][3]);
        }
    }
    __syncthreads();

    // ---- epilogue 2: fused node pass (s_src, s_dst, M) — 16 rows per warp
    for (int rr = 0; rr < 16; rr++) {
        int r = warp * 16 + rr;
        int node = m0 + r;
        float v0 = Hp[r * HPLD + 0 * 32 + lane];
        float v1 = Hp[r * HPLD + 1 * 32 + lane];
        float v2 = Hp[r * HPLD + 2 * 32 + lane];
        float v3 = Hp[r * HPLD + 3 * 32 + lane];
        float p0 = v0 * s_as[lane],       q0 = v0 * s_ad[lane];
        float p1 = v1 * s_as[32 + lane],  q1 = v1 * s_ad[32 + lane];
        float p2 = v2 * s_as[64 + lane],  q2 = v2 * s_ad[64 + lane];
        float p3 = v3 * s_as[96 + lane],  q3 = v3 * s_ad[96 + lane];
#pragma unroll
        for (int o = 16; o; o >>= 1) {
            p0 += __shfl_xor_sync(0xffffffffu, p0, o);
            p1 += __shfl_xor_sync(0xffffffffu, p1, o);
            p2 += __shfl_xor_sync(0xffffffffu, p2, o);
            p3 += __shfl_xor_sync(0xffffffffu, p3, o);
            q0 += __shfl_xor_sync(0xffffffffu, q0, o);
            q1 += __shfl_xor_sync(0xffffffffu, q1, o);
            q2 += __shfl_xor_sync(0xffffffffu, q2, o);
            q3 += __shfl_xor_sync(0xffffffffu, q3, o);
        }
        if (node < NN && lane == 0) {
            d_ssrc[node] = make_float4(p0, p1, p2, p3);
            d_sdst[node] = make_float4(q0, q1, q2, q3);
        }
        float hm = 0.25f * (v0 + v1 + v2 + v3);
        s_hm[warp][lane] = hm;
        __syncwarp();
        float m = 0.f;
#pragma unroll
        for (int l = 0; l < 32; l++) m += s_hm[warp][l] * s_mwT[l * 32 + lane];
        if (node < NN) d_M[(size_t)node * DK + lane] = m;
        __syncwarp();
    }
}

// ---------------- K2: edge pass 1 (logits max, degree count) --------------
__global__ void __launch_bounds__(256) k_edge1(const void* __restrict__ ei,
                                               const float* __restrict__ sim) {
    int e = blockIdx.x * 256 + threadIdx.x;
    int lane = threadIdx.x & 31, warp = threadIdx.x >> 5;
    float4 l = make_float4(-INFINITY, -INFINITY, -INFINITY, -INFINITY);
    if (e < EE) {
        int s, d;
        load_edge(ei, e, s, d);
        float4 a = d_ssrc[s];
        float4 b = d_sdst[d];
        float si = sim[e];
        l.x = a.x + b.x + si; l.y = a.y + b.y + si;
        l.z = a.z + b.z + si; l.w = a.w + b.w + si;
        l.x = l.x >= 0.f ? l.x : NEG * l.x;
        l.y = l.y >= 0.f ? l.y : NEG * l.y;
        l.z = l.z >= 0.f ? l.z : NEG * l.z;
        l.w = l.w >= 0.f ? l.w : NEG * l.w;
        atomicAdd(&d_deg[d], 1);
    }
    float4 m = l;
#pragma unroll
    for (int o = 16; o; o >>= 1) {
        m.x = fmaxf(m.x, __shfl_xor_sync(0xffffffffu, m.x, o));
        m.y = fmaxf(m.y, __shfl_xor_sync(0xffffffffu, m.y, o));
        m.z = fmaxf(m.z, __shfl_xor_sync(0xffffffffu, m.z, o));
        m.w = fmaxf(m.w, __shfl_xor_sync(0xffffffffu, m.w, o));
    }
    __shared__ float4 swm[8];
    if (lane == 0) swm[warp] = m;
    __syncthreads();
    if (warp == 0) {
        float4 mm = (lane < 8) ? swm[lane]
                               : make_float4(-INFINITY, -INFINITY, -INFINITY, -INFINITY);
#pragma unroll
        for (int o = 4; o; o >>= 1) {
            mm.x = fmaxf(mm.x, __shfl_xor_sync(0xffffffffu, mm.x, o));
            mm.y = fmaxf(mm.y, __shfl_xor_sync(0xffffffffu, mm.y, o));
            mm.z = fmaxf(mm.z, __shfl_xor_sync(0xffffffffu, mm.z, o));
            mm.w = fmaxf(mm.w, __shfl_xor_sync(0xffffffffu, mm.w, o));
        }
        if (lane == 0) {
            atomicMax(&d_gmax[0], f2okey(mm.x));
            atomicMax(&d_gmax[1], f2okey(mm.y));
            atomicMax(&d_gmax[2], f2okey(mm.z));
            atomicMax(&d_gmax[3], f2okey(mm.w));
        }
    }
}

// ---------------- K3: bucket offsets via warp-batched atomic --------------
__global__ void k_off() {
    int i = blockIdx.x * 256 + threadIdx.x;
    int lane = threadIdx.x & 31;
    int v = (i < NN) ? d_deg[i] : 0;
    int x = v;
#pragma unroll
    for (int o = 1; o < 32; o <<= 1) {
        int y = __shfl_up_sync(0xffffffffu, x, o);
        if (lane >= o) x += y;
    }
    int excl = x - v;
    int tot = __shfl_sync(0xffffffffu, x, 31);
    int base = 0;
    if (lane == 31) base = atomicAdd(&d_total, tot);
    base = __shfl_sync(0xffffffffu, base, 31);
    if (i < NN) { d_off[i] = base + excl; d_cur[i] = base + excl; }
}

// ---------------- K4: edge pass 2 (recompute logits, exp, scatter) --------
__global__ void __launch_bounds__(256) k_edge2(const void* __restrict__ ei,
                                               const float* __restrict__ sim) {
    int e = blockIdx.x * 256 + threadIdx.x;
    if (e >= EE) return;
    int s, d;
    load_edge(ei, e, s, d);
    float4 a = d_ssrc[s];
    float4 b = d_sdst[d];
    float si = sim[e];
    float4 l;
    l.x = a.x + b.x + si; l.y = a.y + b.y + si;
    l.z = a.z + b.z + si; l.w = a.w + b.w + si;
    l.x = l.x >= 0.f ? l.x : NEG * l.x;
    l.y = l.y >= 0.f ? l.y : NEG * l.y;
    l.z = l.z >= 0.f ? l.z : NEG * l.z;
    l.w = l.w >= 0.f ? l.w : NEG * l.w;
    float g0 = okey2f(d_gmax[0]), g1 = okey2f(d_gmax[1]);
    float g2 = okey2f(d_gmax[2]), g3 = okey2f(d_gmax[3]);
    float4 ex = make_float4(expf(l.x - g0), expf(l.y - g1),
                            expf(l.z - g2), expf(l.w - g3));
    int pos = atomicAdd(&d_cur[d], 1);
    d_expe[pos] = ex;
    d_srcp[pos] = s;
}

// ---------------- K5: per-dst-node softmax + aggregation (single pass) ----
__global__ void __launch_bounds__(256) k_out(float* __restrict__ out_h) {
    int tid = threadIdx.x, lane = tid & 31, warp = tid >> 5;
    int node = blockIdx.x * 8 + warp;
    if (node >= NN) return;
    int start = d_off[node];
    int deg   = d_deg[node];

    int myh = lane >> 3;
    float4 den = make_float4(0.f, 0.f, 0.f, 0.f);
    float4 acc = make_float4(0.f, 0.f, 0.f, 0.f);
#pragma unroll 4
    for (int i = 0; i < deg; i++) {
        float4 ex = d_expe[start + i];   // broadcast across warp
        int s = d_srcp[start + i];
        den.x += ex.x; den.y += ex.y; den.z += ex.z; den.w += ex.w;
        float a = (myh == 0) ? ex.x : (myh == 1) ? ex.y : (myh == 2) ? ex.z : ex.w;
        uint2 hraw = *(const uint2*)&d_Hp16[(size_t)s * OUTD + (lane << 2)];
        float2 f01 = __half22float2(*(const __half2*)&hraw.x);
        float2 f23 = __half22float2(*(const __half2*)&hraw.y);
        acc.x += a * f01.x; acc.y += a * f01.y;
        acc.z += a * f23.x; acc.w += a * f23.y;
    }
    float4 rd = make_float4(1.f / (den.x + 1e-12f), 1.f / (den.y + 1e-12f),
                            1.f / (den.z + 1e-12f), 1.f / (den.w + 1e-12f));
    if (lane == 0) d_rd[node] = rd;
    float r = (myh == 0) ? rd.x : (myh == 1) ? rd.y : (myh == 2) ? rd.z : rd.w;
    *(float4*)&out_h[(size_t)node * OUTD + (lane << 2)] =
        make_float4(acc.x * r, acc.y * r, acc.z * r, acc.w * r);
}

// ---------------- K6: fused msg copy + coalesced alpha ---------------------
#define MSGB (EE * 8 / 256)   // 25000 blocks for msg copy
#define ALPB (EE / 256)       // 3125 blocks for alpha
__global__ void __launch_bounds__(256) k_post(const void* __restrict__ ei,
                                              const float* __restrict__ sim,
                                              float* __restrict__ out_msg,
                                              float* __restrict__ out_alpha) {
    if (blockIdx.x < MSGB) {
        int idx = blockIdx.x * 256 + threadIdx.x;
        int e = idx >> 3;
        int q = (idx & 7) << 2;
        int s, d;
        load_edge(ei, e, s, d);
        float4 v = *(const float4*)&d_M[(size_t)s * DK + q];
        *(float4*)&out_msg[(size_t)e * DK + q] = v;
    } else {
        int e = (blockIdx.x - MSGB) * 256 + threadIdx.x;
        if (e >= EE) return;
        int s, d;
        load_edge(ei, e, s, d);
        float4 a = d_ssrc[s];
        float4 b = d_sdst[d];
        float si = sim[e];
        float4 l;
        l.x = a.x + b.x + si; l.y = a.y + b.y + si;
        l.z = a.z + b.z + si; l.w = a.w + b.w + si;
        l.x = l.x >= 0.f ? l.x : NEG * l.x;
        l.y = l.y >= 0.f ? l.y : NEG * l.y;
        l.z = l.z >= 0.f ? l.z : NEG * l.z;
        l.w = l.w >= 0.f ? l.w : NEG * l.w;
        float g0 = okey2f(d_gmax[0]), g1 = okey2f(d_gmax[1]);
        float g2 = okey2f(d_gmax[2]), g3 = okey2f(d_gmax[3]);
        float4 rd = d_rd[d];
        out_alpha[e] = 0.25f * (expf(l.x - g0) * rd.x + expf(l.y - g1) * rd.y +
                                expf(l.z - g2) * rd.z + expf(l.w - g3) * rd.w);
    }
}

// ---------------- launcher ------------------------------------------------
#define GEMM_SMEM 81920   // 2 stages x 4 arrays x 128x40 bf16; epilogue 128x132 f32 fits

extern "C" void kernel_launch(void* const* d_in, const int* in_sizes, int n_in,
                              void* d_out, int out_size) {
    const float* H    = (const float*)d_in[0];
    const void*  ei   = d_in[1];
    const float* sim  = (const float*)d_in[2];
    const float* W    = (const float*)d_in[3];
    const float* asrc = (const float*)d_in[4];
    const float* adst = (const float*)d_in[5];
    const float* mw   = (const float*)d_in[6];

    float* out       = (float*)d_out;
    float* out_h     = out;                       // [N,128]
    float* out_alpha = out + (size_t)NN * OUTD;   // [E]
    float* out_msg   = out_alpha + EE;            // [E,32]

    cudaFuncSetAttribute(k_gemm_mma,
                         cudaFuncAttributeMaxDynamicSharedMemorySize, GEMM_SMEM);

    k_gemm_mma<<<(NN + GBM - 1) / GBM, 256, GEMM_SMEM>>>(H, W, asrc, adst, mw,
                                                         (const unsigned*)ei);
    k_edge1   <<<EE / 256, 256>>>(ei, sim);
    k_off     <<<(NN + 255) / 256, 256>>>();
    k_edge2   <<<EE / 256, 256>>>(ei, sim);
    k_out     <<<(NN + 7) / 8, 256>>>(out_h);
    k_post    <<<MSGB + ALPB, 256>>>(ei, sim, out_msg, out_alpha);
}